// round 2
// baseline (speedup 1.0000x reference)
#include <cuda_runtime.h>

#define DIMC 128
#define HEADS 8
#define HD 16
#define HH 32
#define WWDIM 32
#define ZZ 8
#define NPTS 8192   // 32*32*8
#define NXV 1024    // 16*16*4
#define KWIN 5

// Scratch (device globals; no runtime allocation allowed)
__device__ float g_stats_x[DIMC * 2];          // mean, rstd per channel of x
__device__ float g_stats_s[DIMC * 2];          // mean, rstd per channel of skip
__device__ float g_q[HEADS * NXV * HD];        // [head][m][d]   (unique voxels only)
__device__ float g_k[HEADS * NPTS * HD];       // [head][n][d]
__device__ float g_v[HEADS * NPTS * HD];       // [head][n][d]
__device__ float g_oT[DIMC * NPTS];            // [j][n] transposed attention output

// ---------------------------------------------------------------------------
// Kernel 1: per-channel instance-norm statistics for x (1024 elems) and skip
// (8192 elems). blockIdx.x in [0,256): first 128 -> x, rest -> skip.
// ---------------------------------------------------------------------------
__global__ void stats_kernel(const float* __restrict__ x,
                             const float* __restrict__ skip) {
    int c = blockIdx.x;
    const float* src;
    int n;
    float* dst;
    if (c < DIMC) { src = x + c * NXV;            n = NXV;  dst = g_stats_x + c * 2; }
    else          { src = skip + (c - DIMC) * NPTS; n = NPTS; dst = g_stats_s + (c - DIMC) * 2; }

    float s = 0.f, s2 = 0.f;
    for (int i = threadIdx.x; i < n; i += 256) {
        float v = src[i];
        s += v; s2 += v * v;
    }
    __shared__ float sh1[8], sh2[8];
    #pragma unroll
    for (int o = 16; o; o >>= 1) {
        s  += __shfl_down_sync(0xffffffffu, s,  o);
        s2 += __shfl_down_sync(0xffffffffu, s2, o);
    }
    int wid = threadIdx.x >> 5, lid = threadIdx.x & 31;
    if (lid == 0) { sh1[wid] = s; sh2[wid] = s2; }
    __syncthreads();
    if (threadIdx.x == 0) {
        float ts = 0.f, ts2 = 0.f;
        #pragma unroll
        for (int i = 0; i < 8; i++) { ts += sh1[i]; ts2 += sh2[i]; }
        float mean = ts / n;
        float var  = ts2 / n - mean * mean;
        dst[0] = mean;
        dst[1] = rsqrtf(var + 1e-5f);
    }
}

// ---------------------------------------------------------------------------
// Kernel 2: K/V projection GEMM. Out[n][j] = sum_c norm(skip)[n][c] * W[c][j] + b[j]
// 128x128 output tile, 256 threads, 8x8 microtile per thread, k-chunk = 8.
// blockIdx.y = 0 -> K (Wk,bk), 1 -> V (Wv,bv).
// Output layout: [head][n][16].
// ---------------------------------------------------------------------------
__global__ void kv_gemm(const float* __restrict__ skip,
                        const float* __restrict__ Wk, const float* __restrict__ bk,
                        const float* __restrict__ Wv, const float* __restrict__ bv) {
    const float* Wt = blockIdx.y ? Wv : Wk;
    const float* bt = blockIdx.y ? bv : bk;
    float* outp = blockIdx.y ? g_v : g_k;
    int n0 = blockIdx.x * 128;

    __shared__ float As[8][128];    // [kk][row n]
    __shared__ float Bs[8][128];    // [kk][col j]
    __shared__ float sm[DIMC], srs[DIMC];
    if (threadIdx.x < 128) {
        sm[threadIdx.x]  = g_stats_s[threadIdx.x * 2];
        srs[threadIdx.x] = g_stats_s[threadIdx.x * 2 + 1];
    }
    __syncthreads();

    float acc[8][8];
    #pragma unroll
    for (int i = 0; i < 8; i++)
        #pragma unroll
        for (int j = 0; j < 8; j++) acc[i][j] = 0.f;

    int tx = threadIdx.x & 15, ty = threadIdx.x >> 4;

    for (int c0 = 0; c0 < DIMC; c0 += 8) {
        __syncthreads();
        #pragma unroll
        for (int i = 0; i < 4; i++) {
            int idx = i * 256 + threadIdx.x;
            int kk = idx >> 7, r = idx & 127;
            int c = c0 + kk;
            As[kk][r] = (skip[c * NPTS + n0 + r] - sm[c]) * srs[c];
            Bs[kk][r] = Wt[c * DIMC + r];
        }
        __syncthreads();
        #pragma unroll
        for (int kk = 0; kk < 8; kk++) {
            float a[8], b[8];
            *(float4*)(a)     = *(const float4*)&As[kk][ty * 8];
            *(float4*)(a + 4) = *(const float4*)&As[kk][ty * 8 + 4];
            *(float4*)(b)     = *(const float4*)&Bs[kk][tx * 8];
            *(float4*)(b + 4) = *(const float4*)&Bs[kk][tx * 8 + 4];
            #pragma unroll
            for (int i = 0; i < 8; i++)
                #pragma unroll
                for (int j = 0; j < 8; j++)
                    acc[i][j] += a[i] * b[j];
        }
    }

    #pragma unroll
    for (int i = 0; i < 8; i++) {
        int n = n0 + ty * 8 + i;
        #pragma unroll
        for (int jj = 0; jj < 8; jj++) {
            int j = tx * 8 + jj;
            float val = acc[i][jj] + bt[j];
            outp[(j >> 4) * (NPTS * HD) + n * HD + (j & 15)] = val;
        }
    }
}

// ---------------------------------------------------------------------------
// Kernel 3: Q projection GEMM on the 1024 unique (pre-upsample) voxels.
// q = (norm(x) @ Wq + bq) * 0.25
// ---------------------------------------------------------------------------
__global__ void q_gemm(const float* __restrict__ x,
                       const float* __restrict__ Wq, const float* __restrict__ bq) {
    int n0 = blockIdx.x * 128;

    __shared__ float As[8][128];
    __shared__ float Bs[8][128];
    __shared__ float sm[DIMC], srs[DIMC];
    if (threadIdx.x < 128) {
        sm[threadIdx.x]  = g_stats_x[threadIdx.x * 2];
        srs[threadIdx.x] = g_stats_x[threadIdx.x * 2 + 1];
    }
    __syncthreads();

    float acc[8][8];
    #pragma unroll
    for (int i = 0; i < 8; i++)
        #pragma unroll
        for (int j = 0; j < 8; j++) acc[i][j] = 0.f;

    int tx = threadIdx.x & 15, ty = threadIdx.x >> 4;

    for (int c0 = 0; c0 < DIMC; c0 += 8) {
        __syncthreads();
        #pragma unroll
        for (int i = 0; i < 4; i++) {
            int idx = i * 256 + threadIdx.x;
            int kk = idx >> 7, r = idx & 127;
            int c = c0 + kk;
            As[kk][r] = (x[c * NXV + n0 + r] - sm[c]) * srs[c];
            Bs[kk][r] = Wq[c * DIMC + r];
        }
        __syncthreads();
        #pragma unroll
        for (int kk = 0; kk < 8; kk++) {
            float a[8], b[8];
            *(float4*)(a)     = *(const float4*)&As[kk][ty * 8];
            *(float4*)(a + 4) = *(const float4*)&As[kk][ty * 8 + 4];
            *(float4*)(b)     = *(const float4*)&Bs[kk][tx * 8];
            *(float4*)(b + 4) = *(const float4*)&Bs[kk][tx * 8 + 4];
            #pragma unroll
            for (int i = 0; i < 8; i++)
                #pragma unroll
                for (int j = 0; j < 8; j++)
                    acc[i][j] += a[i] * b[j];
        }
    }

    #pragma unroll
    for (int i = 0; i < 8; i++) {
        int n = n0 + ty * 8 + i;
        #pragma unroll
        for (int jj = 0; jj < 8; jj++) {
            int j = tx * 8 + jj;
            float val = (acc[i][jj] + bq[j]) * 0.25f;   // HEAD_DIM^-0.5
            g_q[(j >> 4) * (NXV * HD) + n * HD + (j & 15)] = val;
        }
    }
}

// ---------------------------------------------------------------------------
// Kernel 4: neighborhood attention. Grid (8 hblk, 8 wblk, 8 heads),
// block = 128 threads = 4x4x8 spatial tile, one point per thread.
// k/v halo window (8x8x8 positions x 16 f32, padded stride 20 for
// conflict-free LDS.128) + rpb slice in dynamic smem (~85KB -> 2 blocks/SM).
// Online softmax over the 125 neighbors.
// ---------------------------------------------------------------------------
__global__ void attn_kernel(const float* __restrict__ rpb) {
    extern __shared__ float smem[];
    float* sk = smem;                   // 512*20
    float* sv = smem + 512 * 20;        // 512*20
    float* sb = smem + 2 * 512 * 20;    // 729

    int head = blockIdx.z;
    int h0 = blockIdx.x * 4, w0 = blockIdx.y * 4;
    int hlo = min(max(h0 - 2, 0), HH - KWIN);
    int wlo = min(max(w0 - 2, 0), WWDIM - KWIN);
    int tid = threadIdx.x;

    for (int i = tid; i < 729; i += 128) sb[i] = rpb[head * 729 + i];

    const float* gk = g_k + head * (NPTS * HD);
    const float* gv = g_v + head * (NPTS * HD);
    for (int idx = tid; idx < 2048; idx += 128) {
        int pos = idx >> 2, d4 = idx & 3;
        int wz = pos & 7;
        int t = pos >> 3;
        int wwi = t & 7, wh = t >> 3;
        int gh = min(hlo + wh, HH - 1);
        int gw = min(wlo + wwi, WWDIM - 1);
        int n = gh * 256 + gw * 8 + wz;
        *(float4*)(sk + pos * 20 + d4 * 4) = *(const float4*)(gk + n * HD + d4 * 4);
        *(float4*)(sv + pos * 20 + d4 * 4) = *(const float4*)(gv + n * HD + d4 * 4);
    }
    __syncthreads();

    int dh = tid >> 5, dw = (tid >> 3) & 3, z = tid & 7;
    int h = h0 + dh, w = w0 + dw;
    int sh = min(max(h - 2, 0), HH - KWIN);
    int sw = min(max(w - 2, 0), WWDIM - KWIN);
    int sz = min(max(z - 2, 0), ZZ - KWIN);
    int m = (h >> 1) * 64 + (w >> 1) * 4 + (z >> 1);

    float q[16];
    {
        const float4* qp = (const float4*)(g_q + (head * NXV + m) * HD);
        ((float4*)q)[0] = qp[0];
        ((float4*)q)[1] = qp[1];
        ((float4*)q)[2] = qp[2];
        ((float4*)q)[3] = qp[3];
    }

    int bh = sh - h + 4, bw = sw - w + 4, bz = sz - z + 4;

    float mx = -1e30f, sum = 0.f;
    float acc[16];
    #pragma unroll
    for (int d = 0; d < 16; d++) acc[d] = 0.f;

    for (int jh = 0; jh < 5; jh++) {
        int wh = sh + jh - hlo;
        for (int jw = 0; jw < 5; jw++) {
            int wwi = sw + jw - wlo;
            int posb = (wh * 8 + wwi) * 8 + sz;
            const float* bp = sb + (bh + jh) * 81 + (bw + jw) * 9 + bz;
            #pragma unroll
            for (int jz = 0; jz < 5; jz++) {
                const float* kp = sk + (posb + jz) * 20;
                float l = bp[jz];
                #pragma unroll
                for (int d = 0; d < 16; d += 4) {
                    float4 k4 = *(const float4*)(kp + d);
                    l += q[d] * k4.x + q[d + 1] * k4.y + q[d + 2] * k4.z + q[d + 3] * k4.w;
                }
                float nm = fmaxf(mx, l);
                float corr = __expf(mx - nm);
                float p = __expf(l - nm);
                sum = sum * corr + p;
                const float* vp = sv + (posb + jz) * 20;
                #pragma unroll
                for (int d = 0; d < 16; d += 4) {
                    float4 v4 = *(const float4*)(vp + d);
                    acc[d]     = acc[d]     * corr + p * v4.x;
                    acc[d + 1] = acc[d + 1] * corr + p * v4.y;
                    acc[d + 2] = acc[d + 2] * corr + p * v4.z;
                    acc[d + 3] = acc[d + 3] * corr + p * v4.w;
                }
                mx = nm;
            }
        }
    }

    float inv = 1.f / sum;
    int n = h * 256 + w * 8 + z;
    #pragma unroll
    for (int d = 0; d < 16; d++)
        g_oT[(head * HD + d) * NPTS + n] = acc[d] * inv;
}

// ---------------------------------------------------------------------------
// Kernel 5: output projection with transposed write.
// out[c][n] = sum_j oT[j][n] * Wo[j][c] + bo[c]
// Tile: 128 c-rows x 128 n-cols; fully coalesced loads and stores.
// ---------------------------------------------------------------------------
__global__ void proj_gemm(const float* __restrict__ Wo, const float* __restrict__ bo,
                          float* __restrict__ outp) {
    int n0 = blockIdx.x * 128;

    __shared__ float As[8][128];   // [kk][c]  = Wo[j][c]
    __shared__ float Bs[8][128];   // [kk][n]  = oT[j][n]

    float acc[8][8];
    #pragma unroll
    for (int i = 0; i < 8; i++)
        #pragma unroll
        for (int j = 0; j < 8; j++) acc[i][j] = 0.f;

    int tx = threadIdx.x & 15, ty = threadIdx.x >> 4;

    for (int j0 = 0; j0 < DIMC; j0 += 8) {
        __syncthreads();
        #pragma unroll
        for (int i = 0; i < 4; i++) {
            int idx = i * 256 + threadIdx.x;
            int kk = idx >> 7, r = idx & 127;
            As[kk][r] = Wo[(j0 + kk) * DIMC + r];
            Bs[kk][r] = g_oT[(j0 + kk) * NPTS + n0 + r];
        }
        __syncthreads();
        #pragma unroll
        for (int kk = 0; kk < 8; kk++) {
            float a[8], b[8];
            *(float4*)(a)     = *(const float4*)&As[kk][ty * 8];
            *(float4*)(a + 4) = *(const float4*)&As[kk][ty * 8 + 4];
            *(float4*)(b)     = *(const float4*)&Bs[kk][tx * 8];
            *(float4*)(b + 4) = *(const float4*)&Bs[kk][tx * 8 + 4];
            #pragma unroll
            for (int i = 0; i < 8; i++)
                #pragma unroll
                for (int j = 0; j < 8; j++)
                    acc[i][j] += a[i] * b[j];
        }
    }

    #pragma unroll
    for (int i = 0; i < 8; i++) {
        int c = ty * 8 + i;
        float bias = bo[c];
        float* op = outp + c * NPTS + n0 + tx * 8;
        float4 v0 = make_float4(acc[i][0] + bias, acc[i][1] + bias,
                                acc[i][2] + bias, acc[i][3] + bias);
        float4 v1 = make_float4(acc[i][4] + bias, acc[i][5] + bias,
                                acc[i][6] + bias, acc[i][7] + bias);
        *(float4*)(op)     = v0;
        *(float4*)(op + 4) = v1;
    }
}

// ---------------------------------------------------------------------------
extern "C" void kernel_launch(void* const* d_in, const int* in_sizes, int n_in,
                              void* d_out, int out_size) {
    const float* x    = (const float*)d_in[0];
    const float* skip = (const float*)d_in[1];
    const float* Wq   = (const float*)d_in[2];
    const float* bq   = (const float*)d_in[3];
    const float* Wk   = (const float*)d_in[4];
    const float* bk   = (const float*)d_in[5];
    const float* Wv   = (const float*)d_in[6];
    const float* bv   = (const float*)d_in[7];
    const float* rpb  = (const float*)d_in[8];
    const float* Wo   = (const float*)d_in[9];
    const float* bo   = (const float*)d_in[10];
    float* outp = (float*)d_out;

    const int attn_smem = (2 * 512 * 20 + 736) * 4;   // ~84.9 KB
    cudaFuncSetAttribute(attn_kernel, cudaFuncAttributeMaxDynamicSharedMemorySize,
                         attn_smem);

    stats_kernel<<<256, 256>>>(x, skip);
    kv_gemm<<<dim3(64, 2), 256>>>(skip, Wk, bk, Wv, bv);
    q_gemm<<<8, 256>>>(x, Wq, bq);
    attn_kernel<<<dim3(8, 8, 8), 128, attn_smem>>>(rpb);
    proj_gemm<<<64, 256>>>(Wo, bo, outp);
}

// round 3
// speedup vs baseline: 1.5239x; 1.5239x over previous
#include <cuda_runtime.h>
#include <cuda_fp16.h>

#define DIMC 128
#define HEADS 8
#define HD 16
#define HH 32
#define WW 32
#define ZZ 8
#define NPTS 8192   // 32*32*8
#define NXV 1024    // 16*16*4

// Scratch (device globals)
__device__ float  g_stats_x[DIMC * 2];
__device__ float  g_stats_s[DIMC * 2];
__device__ __half2 g_q16[HEADS * NXV * 8];    // [head][m][8 half2]
__device__ __half2 g_k16[HEADS * NPTS * 8];   // [head][n][8 half2]
__device__ __half2 g_v16[HEADS * NPTS * 8];
__device__ float  g_oT[DIMC * NPTS];          // [j][n]

// ---------------------------------------------------------------------------
// Kernel 1: instance-norm statistics
// ---------------------------------------------------------------------------
__global__ void stats_kernel(const float* __restrict__ x,
                             const float* __restrict__ skip) {
    int c = blockIdx.x;
    const float* src; int n; float* dst;
    if (c < DIMC) { src = x + c * NXV;              n = NXV;  dst = g_stats_x + c * 2; }
    else          { src = skip + (c - DIMC) * NPTS; n = NPTS; dst = g_stats_s + (c - DIMC) * 2; }

    float s = 0.f, s2 = 0.f;
    for (int i = threadIdx.x; i < n; i += 256) {
        float v = src[i];
        s += v; s2 += v * v;
    }
    __shared__ float sh1[8], sh2[8];
    #pragma unroll
    for (int o = 16; o; o >>= 1) {
        s  += __shfl_down_sync(0xffffffffu, s,  o);
        s2 += __shfl_down_sync(0xffffffffu, s2, o);
    }
    int wid = threadIdx.x >> 5, lid = threadIdx.x & 31;
    if (lid == 0) { sh1[wid] = s; sh2[wid] = s2; }
    __syncthreads();
    if (threadIdx.x == 0) {
        float ts = 0.f, ts2 = 0.f;
        #pragma unroll
        for (int i = 0; i < 8; i++) { ts += sh1[i]; ts2 += sh2[i]; }
        float mean = ts / n;
        float var  = ts2 / n - mean * mean;
        dst[0] = mean;
        dst[1] = rsqrtf(var + 1e-5f);
    }
}

// ---------------------------------------------------------------------------
// Kernel 2: K/V GEMM, tile 64n x 128j, 256 thr, microtile 4x8.
// grid (128 n-tiles, 2 mats). Output packed half2 [head][n][8].
// ---------------------------------------------------------------------------
__global__ __launch_bounds__(256) void kv_gemm(
        const float* __restrict__ skip,
        const float* __restrict__ Wk, const float* __restrict__ bk,
        const float* __restrict__ Wv, const float* __restrict__ bv) {
    const float* Wt = blockIdx.y ? Wv : Wk;
    const float* bt = blockIdx.y ? bv : bk;
    __half2* outp = blockIdx.y ? g_v16 : g_k16;
    int n0 = blockIdx.x * 64;
    int tid = threadIdx.x;

    __shared__ float As[8][64];
    __shared__ float Bs[8][128];
    __shared__ float sm[DIMC], srs[DIMC];
    if (tid < 128) {
        sm[tid]  = g_stats_s[tid * 2];
        srs[tid] = g_stats_s[tid * 2 + 1];
    }

    float acc[4][8];
    #pragma unroll
    for (int i = 0; i < 4; i++)
        #pragma unroll
        for (int j = 0; j < 8; j++) acc[i][j] = 0.f;

    int tx = tid & 15, ty = tid >> 4;

    for (int c0 = 0; c0 < DIMC; c0 += 8) {
        __syncthreads();
        #pragma unroll
        for (int i = 0; i < 2; i++) {
            int idx = i * 256 + tid;
            int kk = idx >> 6, r = idx & 63;
            int c = c0 + kk;
            As[kk][r] = (skip[c * NPTS + n0 + r] - sm[c]) * srs[c];
        }
        #pragma unroll
        for (int i = 0; i < 4; i++) {
            int idx = i * 256 + tid;
            int kk = idx >> 7, r = idx & 127;
            Bs[kk][r] = Wt[(c0 + kk) * DIMC + r];
        }
        __syncthreads();
        #pragma unroll
        for (int kk = 0; kk < 8; kk++) {
            float a[4], b[8];
            *(float4*)(a)     = *(const float4*)&As[kk][ty * 4];
            *(float4*)(b)     = *(const float4*)&Bs[kk][tx * 8];
            *(float4*)(b + 4) = *(const float4*)&Bs[kk][tx * 8 + 4];
            #pragma unroll
            for (int i = 0; i < 4; i++)
                #pragma unroll
                for (int j = 0; j < 8; j++)
                    acc[i][j] += a[i] * b[j];
        }
    }

    float bb[8];
    #pragma unroll
    for (int j = 0; j < 8; j++) bb[j] = bt[tx * 8 + j];
    int head = tx >> 1;
    int dh0  = (tx & 1) * 4;
    #pragma unroll
    for (int i = 0; i < 4; i++) {
        int n = n0 + ty * 4 + i;
        __half2* op = outp + (head * NPTS + n) * 8 + dh0;
        #pragma unroll
        for (int jj = 0; jj < 4; jj++)
            op[jj] = __floats2half2_rn(acc[i][2 * jj] + bb[2 * jj],
                                       acc[i][2 * jj + 1] + bb[2 * jj + 1]);
    }
}

// ---------------------------------------------------------------------------
// Kernel 3: Q GEMM (1024 unique voxels), same tiling, scale 0.25 folded.
// ---------------------------------------------------------------------------
__global__ __launch_bounds__(256) void q_gemm(
        const float* __restrict__ x,
        const float* __restrict__ Wq, const float* __restrict__ bq) {
    int n0 = blockIdx.x * 64;
    int tid = threadIdx.x;

    __shared__ float As[8][64];
    __shared__ float Bs[8][128];
    __shared__ float sm[DIMC], srs[DIMC];
    if (tid < 128) {
        sm[tid]  = g_stats_x[tid * 2];
        srs[tid] = g_stats_x[tid * 2 + 1];
    }

    float acc[4][8];
    #pragma unroll
    for (int i = 0; i < 4; i++)
        #pragma unroll
        for (int j = 0; j < 8; j++) acc[i][j] = 0.f;

    int tx = tid & 15, ty = tid >> 4;

    for (int c0 = 0; c0 < DIMC; c0 += 8) {
        __syncthreads();
        #pragma unroll
        for (int i = 0; i < 2; i++) {
            int idx = i * 256 + tid;
            int kk = idx >> 6, r = idx & 63;
            int c = c0 + kk;
            As[kk][r] = (x[c * NXV + n0 + r] - sm[c]) * srs[c];
        }
        #pragma unroll
        for (int i = 0; i < 4; i++) {
            int idx = i * 256 + tid;
            int kk = idx >> 7, r = idx & 127;
            Bs[kk][r] = Wq[(c0 + kk) * DIMC + r];
        }
        __syncthreads();
        #pragma unroll
        for (int kk = 0; kk < 8; kk++) {
            float a[4], b[8];
            *(float4*)(a)     = *(const float4*)&As[kk][ty * 4];
            *(float4*)(b)     = *(const float4*)&Bs[kk][tx * 8];
            *(float4*)(b + 4) = *(const float4*)&Bs[kk][tx * 8 + 4];
            #pragma unroll
            for (int i = 0; i < 4; i++)
                #pragma unroll
                for (int j = 0; j < 8; j++)
                    acc[i][j] += a[i] * b[j];
        }
    }

    float bb[8];
    #pragma unroll
    for (int j = 0; j < 8; j++) bb[j] = bq[tx * 8 + j];
    int head = tx >> 1;
    int dh0  = (tx & 1) * 4;
    #pragma unroll
    for (int i = 0; i < 4; i++) {
        int n = n0 + ty * 4 + i;
        __half2* op = g_q16 + (head * NXV + n) * 8 + dh0;
        #pragma unroll
        for (int jj = 0; jj < 4; jj++)
            op[jj] = __floats2half2_rn((acc[i][2 * jj] + bb[2 * jj]) * 0.25f,
                                       (acc[i][2 * jj + 1] + bb[2 * jj + 1]) * 0.25f);
    }
}

// ---------------------------------------------------------------------------
// Kernel 4: neighborhood attention. Tile 4(h) x 8(w) x 8(z) = 256 threads.
// Halo 8x12x8 = 768 positions of fp16 k/v in swizzled smem (51KB).
// No-max softmax (logits are O(0.1); exp cannot overflow), fp32 accumulator.
// grid (8 hblk, 4 wblk, 8 heads).
// ---------------------------------------------------------------------------
#define WH 12   // w halo extent
__global__ __launch_bounds__(256, 4) void attn_kernel(const float* __restrict__ rpb) {
    extern __shared__ float smem[];
    float4* sk4 = (float4*)smem;              // 1536 float4 (768 pos * 2)
    float4* sv4 = sk4 + 1536;                 // 1536 float4
    float*  sb  = (float*)(sv4 + 1536);       // 729 bias

    int head = blockIdx.z;
    int h0 = blockIdx.x * 4, w0 = blockIdx.y * 8;
    int hlo = min(max(h0 - 2, 0), HH - 5);
    int wlo = min(max(w0 - 2, 0), WW - 5);
    int tid = threadIdx.x;

    for (int i = tid; i < 729; i += 256) sb[i] = rpb[head * 729 + i];

    const float4* gk4 = (const float4*)g_k16 + head * (NPTS * 2);
    const float4* gv4 = (const float4*)g_v16 + head * (NPTS * 2);
    #pragma unroll
    for (int it = 0; it < 6; it++) {
        int idx = it * 256 + tid;             // 1536 (pos,d4) pairs
        int d4 = idx & 1, pos = idx >> 1;
        int col = pos >> 3, z1 = pos & 7;
        int wh = col / WH, wwi = col - wh * WH;
        int gh = min(hlo + wh, HH - 1);
        int gw = min(wlo + wwi, WW - 1);
        int n = gh * 256 + gw * 8 + z1;
        int s = pos * 2 + (d4 ^ (col & 1));   // XOR swizzle
        sk4[s] = gk4[n * 2 + d4];
        sv4[s] = gv4[n * 2 + d4];
    }
    __syncthreads();

    int z = tid & 7, dw = (tid >> 3) & 7, dh = tid >> 6;
    int h = h0 + dh, w = w0 + dw;
    int sh = min(max(h - 2, 0), HH - 5);
    int sw = min(max(w - 2, 0), WW - 5);
    int sz = min(max(z - 2, 0), ZZ - 5);
    int m = (h >> 1) * 64 + (w >> 1) * 4 + (z >> 1);

    __half2 q2[8];
    {
        const float4* gq4 = (const float4*)g_q16 + (head * NXV + m) * 2;
        float4 qA = gq4[0], qB = gq4[1];
        const __half2* qa = (const __half2*)&qA;
        const __half2* qb = (const __half2*)&qB;
        #pragma unroll
        for (int i = 0; i < 4; i++) { q2[i] = qa[i]; q2[4 + i] = qb[i]; }
    }

    int bh = sh - h + 4, bw = sw - w + 4, bz = sz - z + 4;

    float sum = 0.f;
    float acc[16];
    #pragma unroll
    for (int d = 0; d < 16; d++) acc[d] = 0.f;

    for (int jh = 0; jh < 5; jh++) {
        int colh = (sh + jh - hlo) * WH;
        const float* bph = sb + (bh + jh) * 81 + bz;
        for (int jw = 0; jw < 5; jw++) {
            int col = colh + (sw + jw - wlo);
            int e = col & 1;
            const float4* kp = sk4 + col * 16 + sz * 2;
            const float4* vp = sv4 + col * 16 + sz * 2;
            const float* bp = bph + (bw + jw) * 9;
            #pragma unroll
            for (int jz = 0; jz < 5; jz++) {
                float4 kA = kp[jz * 2 + e];
                float4 kB = kp[jz * 2 + 1 - e];
                const __half2* ka = (const __half2*)&kA;
                const __half2* kb = (const __half2*)&kB;
                __half2 s0 = __hmul2(q2[0], ka[0]);
                __half2 s1 = __hmul2(q2[1], ka[1]);
                s0 = __hfma2(q2[2], ka[2], s0);
                s1 = __hfma2(q2[3], ka[3], s1);
                s0 = __hfma2(q2[4], kb[0], s0);
                s1 = __hfma2(q2[5], kb[1], s1);
                s0 = __hfma2(q2[6], kb[2], s0);
                s1 = __hfma2(q2[7], kb[3], s1);
                float2 lf = __half22float2(__hadd2(s0, s1));
                float l = bp[jz] + lf.x + lf.y;
                float p = __expf(l);
                sum += p;
                float4 vA = vp[jz * 2 + e];
                float4 vB = vp[jz * 2 + 1 - e];
                const __half2* va = (const __half2*)&vA;
                const __half2* vb = (const __half2*)&vB;
                #pragma unroll
                for (int i = 0; i < 4; i++) {
                    float2 f0 = __half22float2(va[i]);
                    float2 f1 = __half22float2(vb[i]);
                    acc[2 * i]         += p * f0.x;
                    acc[2 * i + 1]     += p * f0.y;
                    acc[8 + 2 * i]     += p * f1.x;
                    acc[8 + 2 * i + 1] += p * f1.y;
                }
            }
        }
    }

    float inv = 1.f / sum;
    int n = h * 256 + w * 8 + z;
    #pragma unroll
    for (int d = 0; d < 16; d++)
        g_oT[(head * HD + d) * NPTS + n] = acc[d] * inv;
}

// ---------------------------------------------------------------------------
// Kernel 5: output projection. Tile 64c x 64n, 256 thr, microtile 4x4.
// grid (128 n-tiles, 2 c-tiles).
// ---------------------------------------------------------------------------
__global__ __launch_bounds__(256) void proj_gemm(
        const float* __restrict__ Wo, const float* __restrict__ bo,
        float* __restrict__ outp) {
    int n0 = blockIdx.x * 64;
    int c0 = blockIdx.y * 64;
    int tid = threadIdx.x;

    __shared__ float As[8][64];   // Wo[j][c-slice]
    __shared__ float Bs[8][64];   // oT[j][n-slice]

    float acc[4][4];
    #pragma unroll
    for (int i = 0; i < 4; i++)
        #pragma unroll
        for (int j = 0; j < 4; j++) acc[i][j] = 0.f;

    int tx = tid & 15, ty = tid >> 4;

    for (int j0 = 0; j0 < DIMC; j0 += 8) {
        __syncthreads();
        #pragma unroll
        for (int i = 0; i < 2; i++) {
            int idx = i * 256 + tid;
            int kk = idx >> 6, r = idx & 63;
            As[kk][r] = Wo[(j0 + kk) * DIMC + c0 + r];
            Bs[kk][r] = g_oT[(j0 + kk) * NPTS + n0 + r];
        }
        __syncthreads();
        #pragma unroll
        for (int kk = 0; kk < 8; kk++) {
            float a[4], b[4];
            *(float4*)(a) = *(const float4*)&As[kk][ty * 4];
            *(float4*)(b) = *(const float4*)&Bs[kk][tx * 4];
            #pragma unroll
            for (int i = 0; i < 4; i++)
                #pragma unroll
                for (int j = 0; j < 4; j++)
                    acc[i][j] += a[i] * b[j];
        }
    }

    #pragma unroll
    for (int i = 0; i < 4; i++) {
        int c = c0 + ty * 4 + i;
        float bias = bo[c];
        float4 v = make_float4(acc[i][0] + bias, acc[i][1] + bias,
                               acc[i][2] + bias, acc[i][3] + bias);
        *(float4*)(outp + c * NPTS + n0 + tx * 4) = v;
    }
}

// ---------------------------------------------------------------------------
extern "C" void kernel_launch(void* const* d_in, const int* in_sizes, int n_in,
                              void* d_out, int out_size) {
    const float* x    = (const float*)d_in[0];
    const float* skip = (const float*)d_in[1];
    const float* Wq   = (const float*)d_in[2];
    const float* bq   = (const float*)d_in[3];
    const float* Wk   = (const float*)d_in[4];
    const float* bk   = (const float*)d_in[5];
    const float* Wv   = (const float*)d_in[6];
    const float* bv   = (const float*)d_in[7];
    const float* rpb  = (const float*)d_in[8];
    const float* Wo   = (const float*)d_in[9];
    const float* bo   = (const float*)d_in[10];
    float* outp = (float*)d_out;

    const int attn_smem = (1536 + 1536) * 16 + 736 * 4;   // ~52KB
    cudaFuncSetAttribute(attn_kernel, cudaFuncAttributeMaxDynamicSharedMemorySize,
                         attn_smem);

    stats_kernel<<<256, 256>>>(x, skip);
    kv_gemm<<<dim3(128, 2), 256>>>(skip, Wk, bk, Wv, bv);
    q_gemm<<<16, 256>>>(x, Wq, bq);
    attn_kernel<<<dim3(8, 4, 8), 256, attn_smem>>>(rpb);
    proj_gemm<<<dim3(128, 2), 256>>>(Wo, bo, outp);
}